// round 10
// baseline (speedup 1.0000x reference)
#include <cuda_runtime.h>
#include <cuda_bf16.h>
#include <mma.h>
#include <cstdint>

using namespace nvcuda;

#define B_    16
#define N_    1024
#define M_    1024
#define D_    512
#define NDIAG 2047
#define LOG2E 1.4426950408889634f
#define LN2   0.6931471805599453f
#define NEGW  -1.0e9f
#define STRIPS 8

// DP geometry: 4 CTAs/batch, 4 warps/CTA (1 per SMSP), 64 rows/warp, 2 rows/lane
#define WSTEPS 1087           // 64 + 1023 steps per warp
#define SB_LEN 1104           // per-link smem boundary array length
#define DYN_SMEM (16384 + 3 * SB_LEN * 4 + 32)

// ---------------- device scratch ----------------
__device__ __nv_bfloat16 g_zx[(size_t)B_ * N_ * D_];
__device__ __nv_bfloat16 g_zy[(size_t)B_ * M_ * D_];
// theta in bf16, diag-major [b][d][i], pre-scaled by log2e; +128 diag global pad
__device__ __nv_bfloat16 g_theta_bf[((size_t)B_ * NDIAG + 128) * 1024];
__device__ float g_gpart[B_][8];
__device__ float g_bound[B_][3][2048];   // 3 CTA->CTA links per batch (indexed by diag)
__device__ int   g_prog[B_][STRIPS];     // [b][0..2] = link flags (reset by convgap)

// ---------------- intrinsics ----------------
__device__ __forceinline__ float ex2f_(float x) {
    float y; asm("ex2.approx.ftz.f32 %0, %1;" : "=f"(y) : "f"(x)); return y;
}
__device__ __forceinline__ float lg2f_(float x) {
    float y; asm("lg2.approx.ftz.f32 %0, %1;" : "=f"(y) : "f"(x)); return y;
}
__device__ __forceinline__ int ld_acq(const int* p) {
    int v; asm volatile("ld.acquire.gpu.b32 %0, [%1];" : "=r"(v) : "l"(p) : "memory"); return v;
}
__device__ __forceinline__ void st_rel(int* p, int v) {
    asm volatile("st.release.gpu.b32 [%0], %1;" :: "l"(p), "r"(v) : "memory");
}
__device__ __forceinline__ int ld_acq_cta(const int* p) {
    int v; asm volatile("ld.acquire.cta.b32 %0, [%1];" : "=r"(v) : "l"(p) : "memory"); return v;
}
__device__ __forceinline__ void st_rel_cta(int* p, int v) {
    asm volatile("st.release.cta.b32 [%0], %1;" :: "l"(p), "r"(v) : "memory");
}
__device__ __forceinline__ void cpasync16(unsigned int dst, const void* src) {
    asm volatile("cp.async.cg.shared.global [%0], [%1], 16;" :: "r"(dst), "l"(src));
}

// soft-max merge of (u+A, g, f+A) in log2 domain, plus theta
__device__ __forceinline__ float cellf(float u, float g, float f,
                                       float A, float A2, float th) {
    float h  = fmaxf(u, f);
    float l  = fminf(u, f);
    float m  = fmaxf(h + A, g);
    float lo = fminf(l + A, g);
    float sum = (u + f) + (A2 + g);
    float mid = (sum - m) - lo;
    float e1 = ex2f_(lo - m);
    float e2 = ex2f_(mid - m);
    float r  = lg2f_((1.0f + e1) + e2);
    return (th + m) + r;
}

// ---------------- 1) fused fp32->bf16 convert + gap partial reduce ----------------
__global__ void __launch_bounds__(512) convgap_kernel(const float* __restrict__ zx,
                                                      const float* __restrict__ zy,
                                                      const float* __restrict__ gw) {
    int blk = blockIdx.x;
    int b   = blockIdx.y;
    int c   = threadIdx.x;
    if (blk == 0 && b == 0 && c < B_ * STRIPS) ((int*)g_prog)[c] = -1;

    size_t base = ((size_t)b * N_ + (size_t)blk * 128) * D_ + c;
    const float* px = zx + base;
    const float* py = zy + base;
    __nv_bfloat16* qx = g_zx + base;
    __nv_bfloat16* qy = g_zy + base;
    float sx = 0.f, sy = 0.f;
#pragma unroll 4
    for (int r = 0; r < 128; r++) {
        float vx = px[(size_t)r * D_];
        float vy = py[(size_t)r * D_];
        qx[(size_t)r * D_] = __float2bfloat16(vx);
        qy[(size_t)r * D_] = __float2bfloat16(vy);
        sx += vx; sy += vy;
    }
    float v = sx * (1.0f / N_) * gw[c] + sy * (1.0f / M_) * gw[512 + c];
    __shared__ float red[512];
    red[c] = v;
    __syncthreads();
    for (int st = 256; st > 0; st >>= 1) {
        if (c < st) red[c] += red[c + st];
        __syncthreads();
    }
    if (c == 0) g_gpart[b][blk] = red[0];
}

// ---------------- 2) GEMM theta = zx @ zy^T, bf16 WMMA, smem staged, bf16 diag epilogue ----
__global__ void __launch_bounds__(256) gemm_kernel() {
    __shared__ __align__(16) __nv_bfloat16 sm[2][128 * 72];

    int b  = blockIdx.z;
    int I0 = blockIdx.y * 128;
    int J0 = blockIdx.x * 128;
    const __nv_bfloat16* Ag = g_zx + ((size_t)b * N_ + I0) * D_;
    const __nv_bfloat16* Bg = g_zy + ((size_t)b * M_ + J0) * D_;

    int warpId = threadIdx.x >> 5;
    int wr = warpId & 3;
    int wc = warpId >> 2;

    wmma::fragment<wmma::accumulator, 16, 16, 16, float> acc[2][4];
#pragma unroll
    for (int i = 0; i < 2; i++)
#pragma unroll
        for (int j = 0; j < 4; j++) wmma::fill_fragment(acc[i][j], 0.0f);

    wmma::fragment<wmma::matrix_a, 16, 16, 16, __nv_bfloat16, wmma::row_major> af[2];
    wmma::fragment<wmma::matrix_b, 16, 16, 16, __nv_bfloat16, wmma::col_major> bfr[4];

    int lr  = threadIdx.x >> 3;
    int lcq = threadIdx.x & 7;

    for (int kc = 0; kc < D_; kc += 64) {
#pragma unroll
        for (int p = 0; p < 4; p++) {
            int row = lr + p * 32;
            *(uint4*)&sm[0][row * 72 + lcq * 8] =
                *(const uint4*)&Ag[(size_t)row * D_ + kc + lcq * 8];
            *(uint4*)&sm[1][row * 72 + lcq * 8] =
                *(const uint4*)&Bg[(size_t)row * D_ + kc + lcq * 8];
        }
        __syncthreads();
#pragma unroll
        for (int kk = 0; kk < 64; kk += 16) {
#pragma unroll
            for (int i = 0; i < 2; i++)
                wmma::load_matrix_sync(af[i], &sm[0][(wr * 32 + i * 16) * 72 + kk], 72);
#pragma unroll
            for (int j = 0; j < 4; j++)
                wmma::load_matrix_sync(bfr[j], &sm[1][(wc * 64 + j * 16) * 72 + kk], 72);
#pragma unroll
            for (int i = 0; i < 2; i++)
#pragma unroll
                for (int j = 0; j < 4; j++)
                    wmma::mma_sync(acc[i][j], af[i], bfr[j], acc[i][j]);
        }
        __syncthreads();
    }

    float* tile = (float*)&sm[0][0];
    for (int phase = 0; phase < 2; phase++) {
        if ((wr >> 1) == phase) {
            int lrr = (wr & 1) * 32;
#pragma unroll
            for (int i = 0; i < 2; i++)
#pragma unroll
                for (int j = 0; j < 4; j++)
                    wmma::store_matrix_sync(tile + (size_t)(lrr + i * 16) * 128 + wc * 64 + j * 16,
                                            acc[i][j], 128, wmma::mem_row_major);
        }
        __syncthreads();
        int rowoff = phase * 64;
        for (int e = threadIdx.x; e < 191 * 64; e += 256) {
            int dl = e >> 6;
            int t  = e & 63;
            int li = (dl > 127 ? dl - 127 : 0) + t;
            int lj = dl - li;
            if (li < 64 && lj >= 0 && lj < 128) {
                int gi = I0 + rowoff + li;
                int gj = J0 + lj;
                g_theta_bf[((size_t)b * NDIAG + (gi + gj)) * 1024 + gi] =
                    __float2bfloat16(tile[li * 128 + lj] * LOG2E);
            }
        }
        __syncthreads();
    }
}

// ---------------- 3) wavefront DP: 2 rows/lane, 64 rows/warp, 4 warps/CTA, 4 CTAs/batch ----
// 1 warp per SMSP (no MUFU/issue sharing). Warp->warp via dynamic-smem boundary + cta flags.
// CTA->CTA via g_bound[b][link]/g_prog, 32-diag register blocks prefetched ahead.
// Theta: bf16, 16-diag 2KB chunks via cp.async double-buffered (2 ahead).
__global__ void __launch_bounds__(128) dp_kernel(const float* __restrict__ gb,
                                                 float* __restrict__ out) {
    const int quad = blockIdx.x;               // rows [256*quad, 256*quad+255]
    const int b    = blockIdx.y;
    const int t = threadIdx.x, w = t >> 5, lane = t & 31;
    const int row0w = quad * 256 + w * 64;     // warp's first global row

    extern __shared__ char smem_dyn[];
    float* sBall = (float*)(smem_dyn + 16384);                     // 3 x SB_LEN floats
    int*   sF    = (int*)(smem_dyn + 16384 + 3 * SB_LEN * 4);      // 3 flags
    float* sAp   = (float*)(smem_dyn + 16384 + 3 * SB_LEN * 4 + 28);

    // ---- theta cp.async plumbing: chunk c = local diags 16c..16c+15, 2KB (64 rows/diag) ----
    const char* thw = (const char*)g_theta_bf
        + ((size_t)b * NDIAG + (size_t)row0w) * 2048 + (size_t)row0w * 2;
    const unsigned sdstW = (unsigned)__cvta_generic_to_shared(smem_dyn) + (unsigned)w * 4096u;

#define ISSUE_CHUNK(c)                                                        \
    do {                                                                      \
        unsigned db_ = sdstW + (((c) & 1) ? 2048u : 0u);                      \
        _Pragma("unroll")                                                     \
        for (int u4 = 0; u4 < 4; u4++) {                                      \
            int u_ = lane + 32 * u4;                                          \
            cpasync16(db_ + (unsigned)u_ * 16u,                               \
                      thw + (size_t)(16 * (c) + (u_ >> 3)) * 2048 + (u_ & 7) * 16); \
        }                                                                     \
        asm volatile("cp.async.commit_group;");                               \
    } while (0)

    ISSUE_CHUNK(0);
    ISSUE_CHUNK(1);

    for (int k = t; k < 3 * SB_LEN; k += 128) sBall[k] = NEGW;
    if (t < 3) sF[t] = -1;
    if (t == 0) {
        float a = 0.f;
#pragma unroll
        for (int k = 0; k < 8; k++) a += g_gpart[b][k];
        *sAp = (a + gb[0]) * LOG2E;
    }
    __syncthreads();

    const float A = *sAp, A2 = A + A;

    const bool cs = (w > 0);                   // consume smem boundary
    const bool cg = (w == 0 && quad > 0);      // consume global boundary
    const bool ps = (w < 3);                   // produce smem boundary
    const bool pg = (w == 3 && quad < 3);      // produce global boundary

    const float* sIn = sBall + (size_t)((w > 0) ? (w - 1) : 0) * SB_LEN;
    const int*   fIn = &sF[(w > 0) ? (w - 1) : 0];
    float* sOut = sBall + (size_t)((w < 3) ? w : 0) * SB_LEN;
    int*   fOut = &sF[(w < 3) ? w : 0];

    const float* gsrc  = &g_bound[b][(quad > 0) ? (quad - 1) : 0][0];
    const int*   gfin  = &g_prog[b][(quad > 0) ? (quad - 1) : 0];
    float*       gdstp = &g_bound[b][(quad < 3) ? quad : 0][quad * 256 + 192]; // diag row0w(prod)+P
    int*         gflag = &g_prog[b][(quad < 3) ? quad : 0];
    const int    gbase = quad * 256 - 1;       // consumer boundary diag for step 0
    const int    gcap  = quad * 256 + 1022;    // last diag producer ever writes for this link

    int gcache = -0x40000000, scache = -1;
    float gb0 = NEGW, gb1 = NEGW;              // 32-step global boundary blocks

    // block c32 covers consumer steps q in [32c32, 32c32+31] -> boundary diag gbase+q
    auto gfetch32 = [&](int c32) -> float {
        float v = NEGW;
        int qb = 32 * c32;
        if (qb <= 1023) {
            int tgt = min(gbase + qb + 31, gcap);
            while (gcache < tgt) gcache = ld_acq(gfin);
            if (qb + lane <= 1023) v = __ldcg(gsrc + gbase + qb + lane);
        }
        return v;
    };
    if (cg) gb0 = gfetch32(0);

    // per-lane DP state (rows rbase=lane*2, rbase+1)
    const int rbase = lane * 2;
    float pv0 = NEGW, pv1 = NEGW;              // values at diag p-1
    float q0 = NEGW;                            // row0 value at diag p-2
    float nbp = (quad == 0 && w == 0 && lane == 0) ? 0.0f : NEGW;  // neighbor at p-2

#define DP_STEP(P, O)                                                        \
    {                                                                        \
        unsigned tw = *(const unsigned*)((const char*)tb + (O) * 128 + lane * 4); \
        float bnd;                                                           \
        if (cs) bnd = sIn[(P)];                                              \
        else if (cg) {                                                       \
            float bsel = (((P) >> 5) & 1) ? gb1 : gb0;                       \
            bnd = __shfl_sync(0xffffffffu, bsel, (P) & 31);                  \
        } else bnd = NEGW;                                                   \
        float nbr = __shfl_up_sync(0xffffffffu, pv1, 1);                     \
        float nb = (lane == 0) ? bnd : nbr;                                  \
        float t0 = __uint_as_float(tw << 16);                                \
        float t1 = __uint_as_float(tw & 0xffff0000u);                        \
        float v0 = cellf(nb,  nbp, pv0, A, A2, t0);                          \
        float v1 = cellf(pv0, q0,  pv1, A, A2, t1);                          \
        v0 = ((unsigned)((P) - (rbase + 0)) <= 1023u) ? v0 : NEGW;           \
        v1 = ((unsigned)((P) - (rbase + 1)) <= 1023u) ? v1 : NEGW;           \
        nbp = nb; q0 = pv0;                                                  \
        pv0 = v0; pv1 = v1;                                                  \
        if (lane == 31) {                                                    \
            int e = (P) - 63;                                                \
            if (ps) {                                                        \
                if ((unsigned)e <= 1023u) sOut[e] = v1;                      \
                if (((O) & 7) == 7) st_rel_cta(fOut, e);                     \
            }                                                                \
            if (pg) {                                                        \
                if ((unsigned)e <= 1023u) __stcg(gdstp + (P), v1);           \
                if (((O) & 7) == 7) st_rel(gflag, quad * 256 + 192 + (P));   \
            }                                                                \
        }                                                                    \
    }

    int p = 0;
    for (int c = 0; c < 67; c++) {             // 67 full chunks: steps 0..1071
        asm volatile("cp.async.wait_group 1;");
        __syncwarp();
        const __nv_bfloat16* tb = (const __nv_bfloat16*)(smem_dyn + w * 4096 + (c & 1) * 2048);
        if (cg && ((c & 1) == 0)) {
            int c32 = c >> 1;
            float v = gfetch32(c32 + 1);
            if ((c32 + 1) & 1) gb1 = v; else gb0 = v;
        }
#pragma unroll
        for (int blk = 0; blk < 2; blk++) {
            if (cs) {
                int tgt = min(p + 7, 1023);
                while (scache < tgt) scache = ld_acq_cta(fIn);
            }
#pragma unroll
            for (int k = 0; k < 8; k++) {
                DP_STEP(p, (blk * 8 + k))
                p++;
            }
        }
        ISSUE_CHUNK(c + 2);
    }
    // tail chunk 67: steps 1072..1086 (15 steps)
    {
        asm volatile("cp.async.wait_group 1;");
        __syncwarp();
        const __nv_bfloat16* tb = (const __nv_bfloat16*)(smem_dyn + w * 4096 + (67 & 1) * 2048);
        if (cs) { while (scache < 1023) scache = ld_acq_cta(fIn); }
        if (cg) { gb0 = NEGW; gb1 = NEGW; }    // all boundary rows masked past q=1023
#pragma unroll
        for (int k = 0; k < 8; k++) { DP_STEP(p, k) p++; }
#pragma unroll
        for (int k = 8; k < 15; k++) { DP_STEP(p, k) p++; }
    }
#undef DP_STEP
#undef ISSUE_CHUNK

    if (ps && lane == 31) st_rel_cta(fOut, 4096);
    if (pg && lane == 31) st_rel(gflag, 0x7FFFFFF0);

    // quad 3, warp 3, lane 31, row 1 = global row 1023 at diag 2046 -> V[N][M]
    if (quad == 3 && w == 3 && lane == 31) out[b] = pv1 * LN2;
}

// ---------------- launch ----------------
extern "C" void kernel_launch(void* const* d_in, const int* in_sizes, int n_in,
                              void* d_out, int out_size) {
    (void)in_sizes; (void)n_in; (void)out_size;
    const float* zx = (const float*)d_in[0];
    const float* zy = (const float*)d_in[1];
    const float* gw = (const float*)d_in[2];
    const float* gb = (const float*)d_in[3];
    float* out = (float*)d_out;

    cudaFuncSetAttribute(dp_kernel, cudaFuncAttributeMaxDynamicSharedMemorySize, DYN_SMEM);

    convgap_kernel<<<dim3(8, B_), 512>>>(zx, zy, gw);
    gemm_kernel<<<dim3(8, 8, B_), 256>>>();
    dp_kernel<<<dim3(4, B_), 128, DYN_SMEM>>>(gb, out);
}

// round 13
// speedup vs baseline: 1.7142x; 1.7142x over previous
#include <cuda_runtime.h>
#include <cuda_bf16.h>
#include <mma.h>
#include <cstdint>

using namespace nvcuda;

#define B_    16
#define N_    1024
#define M_    1024
#define D_    512
#define NDIAG 2047
#define LOG2E 1.4426950408889634f
#define LN2   0.6931471805599453f
#define NEGW  -1.0e9f

// DP geometry: 1 CTA/batch, 16 warps (4/SMSP), 64 rows/warp, 2 rows/lane. All links smem.
#define SB_LEN  1104                            // >= 1087 (max step index read unguarded)
#define TH_BYTES (16 * 4096)                    // 16 warps x 2 bufs x 2KB
#define SB_OFF  TH_BYTES                        // 65536
#define FL_OFF  (SB_OFF + 15 * SB_LEN * 4)      // 65536 + 66240 = 131776
#define DYN_SMEM (FL_OFF + 64)                  // 131840 (GEMM needs 36864 <= this)

// ---------------- device scratch ----------------
__device__ __nv_bfloat16 g_zx[(size_t)B_ * N_ * D_];
__device__ __nv_bfloat16 g_zy[(size_t)B_ * M_ * D_];
// theta in bf16, diag-major [b][d][i], pre-scaled by log2e; +128 diag pad for prefetch
__device__ __nv_bfloat16 g_theta_bf[((size_t)B_ * NDIAG + 128) * 1024];
__device__ float g_gpart[B_][16];
__device__ int   g_tprog[B_][15];     // completed GEMM tiles per block-antidiagonal

// ---------------- intrinsics ----------------
__device__ __forceinline__ float ex2f_(float x) {
    float y; asm("ex2.approx.ftz.f32 %0, %1;" : "=f"(y) : "f"(x)); return y;
}
__device__ __forceinline__ float lg2f_(float x) {
    float y; asm("lg2.approx.ftz.f32 %0, %1;" : "=f"(y) : "f"(x)); return y;
}
__device__ __forceinline__ int ld_acq(const int* p) {
    int v; asm volatile("ld.acquire.gpu.b32 %0, [%1];" : "=r"(v) : "l"(p) : "memory"); return v;
}
__device__ __forceinline__ int ld_acq_cta(const int* p) {
    int v; asm volatile("ld.acquire.cta.b32 %0, [%1];" : "=r"(v) : "l"(p) : "memory"); return v;
}
__device__ __forceinline__ void st_rel_cta(int* p, int v) {
    asm volatile("st.release.cta.b32 [%0], %1;" :: "l"(p), "r"(v) : "memory");
}
__device__ __forceinline__ void cpasync16(unsigned int dst, const void* src) {
    asm volatile("cp.async.cg.shared.global [%0], [%1], 16;" :: "r"(dst), "l"(src));
}

// soft-max merge of (u+A, g, f+A) in log2 domain, plus theta
__device__ __forceinline__ float cellf(float u, float g, float f,
                                       float A, float A2, float th) {
    float h  = fmaxf(u, f);
    float l  = fminf(u, f);
    float m  = fmaxf(h + A, g);
    float lo = fminf(l + A, g);
    float sum = (u + f) + (A2 + g);
    float mid = (sum - m) - lo;
    float e1 = ex2f_(lo - m);
    float e2 = ex2f_(mid - m);
    float r  = lg2f_((1.0f + e1) + e2);
    return (th + m) + r;
}

// ---------------- 1) fused fp32->bf16 convert + gap partial reduce ----------------
__global__ void __launch_bounds__(512) convgap_kernel(const float* __restrict__ zx,
                                                      const float* __restrict__ zy,
                                                      const float* __restrict__ gw) {
    int blk = blockIdx.x;           // 0..15 (64 rows each)
    int b   = blockIdx.y;
    int c   = threadIdx.x;          // feature 0..511
    if (blk == 0 && b == 0 && c < B_ * 15) ((int*)g_tprog)[c] = 0;

    size_t base = ((size_t)b * N_ + (size_t)blk * 64) * D_ + c;
    const float* px = zx + base;
    const float* py = zy + base;
    __nv_bfloat16* qx = g_zx + base;
    __nv_bfloat16* qy = g_zy + base;
    float sx = 0.f, sy = 0.f;
#pragma unroll 4
    for (int r = 0; r < 64; r++) {
        float vx = px[(size_t)r * D_];
        float vy = py[(size_t)r * D_];
        qx[(size_t)r * D_] = __float2bfloat16(vx);
        qy[(size_t)r * D_] = __float2bfloat16(vy);
        sx += vx; sy += vy;
    }
    float v = sx * (1.0f / N_) * gw[c] + sy * (1.0f / M_) * gw[512 + c];
    __shared__ float red[512];
    red[c] = v;
    __syncthreads();
    for (int st = 256; st > 0; st >>= 1) {
        if (c < st) red[c] += red[c + st];
        __syncthreads();
    }
    if (c == 0) g_gpart[b][blk] = red[0];
}

// ---------------- 2a) GEMM body (512 threads, dynamic smem, antidiag-ordered) ----------------
__device__ void gemm_body(int g, char* smem) {
    int b     = g & 15;
    int arank = g >> 4;             // tile rank in antidiagonal order
    int a = 0, rem = arank;
    while (true) {
        int sz = 8 - (a > 7 ? a - 7 : 7 - a);
        if (rem < sz) break;
        rem -= sz; a++;
    }
    int bi = (a < 8 ? 0 : a - 7) + rem;
    int bj = a - bi;
    int I0 = bi * 128, J0 = bj * 128;

    __nv_bfloat16* smA = (__nv_bfloat16*)smem;       // 128 x 72
    __nv_bfloat16* smB = smA + 128 * 72;

    const __nv_bfloat16* Ag = g_zx + ((size_t)b * N_ + I0) * D_;
    const __nv_bfloat16* Bg = g_zy + ((size_t)b * M_ + J0) * D_;

    int tid = threadIdx.x;
    int warpId = tid >> 5;          // 0..15
    int wr = warpId & 3;            // 4 warp-rows of 32
    int wc = warpId >> 2;           // 4 warp-cols of 32

    wmma::fragment<wmma::accumulator, 16, 16, 16, float> acc[2][2];
#pragma unroll
    for (int i = 0; i < 2; i++)
#pragma unroll
        for (int j = 0; j < 2; j++) wmma::fill_fragment(acc[i][j], 0.0f);

    wmma::fragment<wmma::matrix_a, 16, 16, 16, __nv_bfloat16, wmma::row_major> af[2];
    wmma::fragment<wmma::matrix_b, 16, 16, 16, __nv_bfloat16, wmma::col_major> bfr[2];

    int lr  = tid >> 3;             // 0..63
    int lcq = tid & 7;              // uint4 column

    for (int kc = 0; kc < D_; kc += 64) {
#pragma unroll
        for (int p = 0; p < 2; p++) {
            int row = lr + p * 64;
            *(uint4*)&smA[row * 72 + lcq * 8] =
                *(const uint4*)&Ag[(size_t)row * D_ + kc + lcq * 8];
            *(uint4*)&smB[row * 72 + lcq * 8] =
                *(const uint4*)&Bg[(size_t)row * D_ + kc + lcq * 8];
        }
        __syncthreads();
#pragma unroll
        for (int kk = 0; kk < 64; kk += 16) {
#pragma unroll
            for (int i = 0; i < 2; i++)
                wmma::load_matrix_sync(af[i], &smA[(wr * 32 + i * 16) * 72 + kk], 72);
#pragma unroll
            for (int j = 0; j < 2; j++)
                wmma::load_matrix_sync(bfr[j], &smB[(wc * 32 + j * 16) * 72 + kk], 72);
#pragma unroll
            for (int i = 0; i < 2; i++)
#pragma unroll
                for (int j = 0; j < 2; j++)
                    wmma::mma_sync(acc[i][j], af[i], bfr[j], acc[i][j]);
        }
        __syncthreads();
    }

    // Epilogue: stage 64x128 float halves, drain in anti-diagonal order (bf16, log2e folded).
    float* tile = (float*)smem;
    for (int phase = 0; phase < 2; phase++) {
        if ((wr >> 1) == phase) {
            int lrr = (wr & 1) * 32;
#pragma unroll
            for (int i = 0; i < 2; i++)
#pragma unroll
                for (int j = 0; j < 2; j++)
                    wmma::store_matrix_sync(tile + (size_t)(lrr + i * 16) * 128 + wc * 32 + j * 16,
                                            acc[i][j], 128, wmma::mem_row_major);
        }
        __syncthreads();
        int rowoff = phase * 64;
        for (int e = tid; e < 191 * 64; e += 512) {
            int dl = e >> 6;
            int t  = e & 63;
            int li = (dl > 127 ? dl - 127 : 0) + t;
            int lj = dl - li;
            if (li < 64 && lj >= 0 && lj < 128) {
                int gi = I0 + rowoff + li;
                int gj = J0 + lj;
                g_theta_bf[((size_t)b * NDIAG + (gi + gj)) * 1024 + gi] =
                    __float2bfloat16(tile[li * 128 + lj] * LOG2E);
            }
        }
        __syncthreads();
    }

    __threadfence();                 // every thread: order its theta stores
    __syncthreads();
    if (tid == 0) atomicAdd(&g_tprog[b][a], 1);
}

// ---------------- 2b) DP body: 16 warps x 64 rows, all-smem links ----------------
__device__ void dp_body(int b, const float* __restrict__ gb, float* __restrict__ out,
                        char* smem) {
    const int t = threadIdx.x, w = t >> 5, lane = t & 31;
    const int row0w = w * 64;

    float* sBall = (float*)(smem + SB_OFF);
    int*   sF    = (int*)(smem + FL_OFF);
    float* sAp   = (float*)(smem + FL_OFF + 60);

    // theta cp.async: chunk c = local diags 16c..16c+15, 2KB (64 rows/diag)
    const char* thw = (const char*)g_theta_bf
        + ((size_t)b * NDIAG + (size_t)row0w) * 2048 + (size_t)row0w * 2;
    const unsigned sdstW = (unsigned)__cvta_generic_to_shared(smem) + (unsigned)w * 4096u;

    int tadv = -1;                  // highest GEMM antidiag known complete

#define POLL_THETA(c)                                                         \
    do {                                                                      \
        int dmax_ = row0w + 16 * (c) + 15; if (dmax_ > 2046) dmax_ = 2046;    \
        int amax_ = dmax_ >> 7; if (amax_ > 14) amax_ = 14;                   \
        while (tadv < amax_) {                                                \
            int a_ = tadv + 1;                                                \
            int sz_ = 8 - (a_ > 7 ? a_ - 7 : 7 - a_);                         \
            if (ld_acq(&g_tprog[b][a_]) == sz_) tadv++;                       \
        }                                                                     \
    } while (0)

#define ISSUE_CHUNK(c)                                                        \
    do {                                                                      \
        unsigned db_ = sdstW + (((c) & 1) ? 2048u : 0u);                      \
        _Pragma("unroll")                                                     \
        for (int u4 = 0; u4 < 4; u4++) {                                      \
            int u_ = lane + 32 * u4;                                          \
            cpasync16(db_ + (unsigned)u_ * 16u,                               \
                      thw + (size_t)(16 * (c) + (u_ >> 3)) * 2048 + (u_ & 7) * 16); \
        }                                                                     \
        asm volatile("cp.async.commit_group;");                               \
    } while (0)

    POLL_THETA(0); ISSUE_CHUNK(0);
    POLL_THETA(1); ISSUE_CHUNK(1);

    for (int k = t; k < 15 * SB_LEN; k += 512) sBall[k] = NEGW;
    if (t < 15) sF[t] = -1;
    if (t == 0) {
        float a = 0.f;
#pragma unroll
        for (int k = 0; k < 16; k++) a += g_gpart[b][k];
        *sAp = (a + gb[0]) * LOG2E;
    }
    __syncthreads();

    const float A = *sAp, A2 = A + A;

    const bool cs = (w > 0);
    const bool ps = (w < 15);
    const float* sIn = sBall + (size_t)((w > 0) ? (w - 1) : 0) * SB_LEN;
    const int*   fIn = &sF[(w > 0) ? (w - 1) : 0];
    float* sOut = sBall + (size_t)((w < 15) ? w : 0) * SB_LEN;
    int*   fOut = &sF[(w < 15) ? w : 0];

    int scache = -1;

    const int rbase = lane * 2;
    float pv0 = NEGW, pv1 = NEGW;   // values at diag p-1
    float q0 = NEGW;                // row0 value at diag p-2
    float nbp = (w == 0 && lane == 0) ? 0.0f : NEGW;   // neighbor at p-2

#define DP_STEP(P, O)                                                        \
    {                                                                        \
        unsigned tw = *(const unsigned*)((const char*)tb + (O) * 128 + lane * 4); \
        float bnd = cs ? sIn[(P)] : NEGW;                                    \
        float nbr = __shfl_up_sync(0xffffffffu, pv1, 1);                     \
        float nb = (lane == 0) ? bnd : nbr;                                  \
        float t0 = __uint_as_float(tw << 16);                                \
        float t1 = __uint_as_float(tw & 0xffff0000u);                        \
        float v0 = cellf(nb,  nbp, pv0, A, A2, t0);                          \
        float v1 = cellf(pv0, q0,  pv1, A, A2, t1);                          \
        v0 = ((unsigned)((P) - (rbase + 0)) <= 1023u) ? v0 : NEGW;           \
        v1 = ((unsigned)((P) - (rbase + 1)) <= 1023u) ? v1 : NEGW;           \
        nbp = nb; q0 = pv0;                                                  \
        pv0 = v0; pv1 = v1;                                                  \
        if (ps && lane == 31) {                                              \
            int e = (P) - 63;                                                \
            if ((unsigned)e <= 1023u) sOut[e] = v1;                          \
            if (((O) & 7) == 7) st_rel_cta(fOut, e);                         \
        }                                                                    \
    }

    int p = 0;
    for (int c = 0; c < 67; c++) {             // 67 full chunks: steps 0..1071
        asm volatile("cp.async.wait_group 1;");
        __syncwarp();
        const __nv_bfloat16* tb = (const __nv_bfloat16*)(smem + w * 4096 + (c & 1) * 2048);
#pragma unroll
        for (int blk = 0; blk < 2; blk++) {
            if (cs) {
                int tgt = min(p + 7, 1023);
                while (scache < tgt) scache = ld_acq_cta(fIn);
            }
#pragma unroll
            for (int k = 0; k < 8; k++) {
                DP_STEP(p, (blk * 8 + k))
                p++;
            }
        }
        POLL_THETA(c + 2);
        ISSUE_CHUNK(c + 2);
    }
    // tail chunk 67: steps 1072..1086 (15 steps)
    {
        asm volatile("cp.async.wait_group 1;");
        __syncwarp();
        const __nv_bfloat16* tb = (const __nv_bfloat16*)(smem + w * 4096 + (67 & 1) * 2048);
        if (cs) { while (scache < 1023) scache = ld_acq_cta(fIn); }
#pragma unroll
        for (int k = 0; k < 8; k++) { DP_STEP(p, k) p++; }
#pragma unroll
        for (int k = 8; k < 15; k++) { DP_STEP(p, k) p++; }
    }
#undef DP_STEP
#undef ISSUE_CHUNK
#undef POLL_THETA

    if (ps && lane == 31) st_rel_cta(fOut, 4096);

    // warp 15, lane 31, row 1 = global row 1023 at diag 2046 -> V[N][M]
    if (w == 15 && lane == 31) out[b] = pv1 * LN2;
}

// ---------------- 2) fused kernel: 16 DP CTAs (first) + 1024 GEMM CTAs ----------------
__global__ void __launch_bounds__(512) fused_kernel(const float* __restrict__ gb,
                                                    float* __restrict__ out) {
    extern __shared__ char smem_dyn[];
    if (blockIdx.x < B_) dp_body(blockIdx.x, gb, out, smem_dyn);
    else                 gemm_body(blockIdx.x - B_, smem_dyn);
}

// ---------------- launch ----------------
extern "C" void kernel_launch(void* const* d_in, const int* in_sizes, int n_in,
                              void* d_out, int out_size) {
    (void)in_sizes; (void)n_in; (void)out_size;
    const float* zx = (const float*)d_in[0];
    const float* zy = (const float*)d_in[1];
    const float* gw = (const float*)d_in[2];
    const float* gb = (const float*)d_in[3];
    float* out = (float*)d_out;

    cudaFuncSetAttribute(fused_kernel, cudaFuncAttributeMaxDynamicSharedMemorySize, DYN_SMEM);

    convgap_kernel<<<dim3(16, B_), 512>>>(zx, zy, gw);
    fused_kernel<<<B_ + 1024, 512, DYN_SMEM>>>(gb, out);
}